// round 14
// baseline (speedup 1.0000x reference)
#include <cuda_runtime.h>
#include <cuda_bf16.h>
#include <math.h>
#include <stdint.h>

#define B_SZ 2048
#define M_SZ 1024
#define D_SZ 64
#define KDIM 128   // 2*D_SZ
#define TILE_ELEMS 16384   // 128x128 bf16 tile
#define TILE_BYTES 32768

// ---------------- device scratch (operands stored as swizzled 128x128 tiles) ----------------
__device__ __nv_bfloat16 g_Xh[16 * TILE_ELEMS];          // [bblock][tile]
__device__ __nv_bfloat16 g_Xl[16 * TILE_ELEMS];
__device__ __nv_bfloat16 g_Bmh[8 * TILE_ELEMS];          // [mblock][tile] rows=m, cols=k
__device__ __nv_bfloat16 g_Bml[8 * TILE_ELEMS];
__device__ __nv_bfloat16 g_PTh[8 * TILE_ELEMS];          // [mblock][tile] rows=outcol, cols=m
__device__ __nv_bfloat16 g_PTl[8 * TILE_ELEMS];
__device__ float2 g_hl[M_SZ];                    // (.x = -0.5*sum(mut^2/Sig + log Sig), .y = Lam)
__device__ float  g_uacc[(size_t)B_SZ * KDIM];   // [b][T1|T2] atomically reduced over mb
__device__ float  g_nacc[B_SZ];                  // norm, atomically reduced
__device__ int    g_cnt[16];                     // per-bblock CTA arrival counter

// ---------------- helpers ----------------
__device__ __forceinline__ uint32_t smem_u32(const void* p) {
    uint32_t a;
    asm("{ .reg .u64 t; cvta.to.shared.u64 t, %1; cvt.u32.u64 %0, t; }" : "=r"(a) : "l"(p));
    return a;
}
// byte offset of element (r, c) inside a swizzled 128x128 bf16 tile
__device__ __forceinline__ uint32_t tile_off(int r, int c) {
    int ch = c >> 3;
    return (uint32_t)(r * 256 + (((ch ^ (r & 7))) << 4) + ((c & 7) << 1));
}
__device__ __forceinline__ void ldmx4(uint32_t* r, uint32_t addr) {
    asm volatile("ldmatrix.sync.aligned.m8n8.x4.shared.b16 {%0,%1,%2,%3}, [%4];"
        : "=r"(r[0]), "=r"(r[1]), "=r"(r[2]), "=r"(r[3]) : "r"(addr));
}
__device__ __forceinline__ void mma16816(float* c, const uint32_t* a, uint32_t b0, uint32_t b1) {
    asm volatile(
        "mma.sync.aligned.m16n8k16.row.col.f32.bf16.bf16.f32 "
        "{%0,%1,%2,%3}, {%4,%5,%6,%7}, {%8,%9}, {%0,%1,%2,%3};"
        : "+f"(c[0]), "+f"(c[1]), "+f"(c[2]), "+f"(c[3])
        : "r"(a[0]), "r"(a[1]), "r"(a[2]), "r"(a[3]), "r"(b0), "r"(b1));
}
__device__ __forceinline__ void bulk_cp(uint32_t dst, const void* src, uint32_t bytes, uint32_t mbar) {
    asm volatile(
        "cp.async.bulk.shared::cluster.global.mbarrier::complete_tx::bytes [%0], [%1], %2, [%3];"
        :: "r"(dst), "l"(src), "r"(bytes), "r"(mbar) : "memory");
}
#define MBAR_INIT(a, n) asm volatile("mbarrier.init.shared.b64 [%0], %1;" :: "r"(a), "r"(n) : "memory")
#define MBAR_EXPECT(a, b) asm volatile("mbarrier.arrive.expect_tx.shared.b64 _, [%0], %1;" :: "r"(a), "r"(b) : "memory")
#define MBAR_WAIT0(a) do { \
    uint32_t _m = (a); uint32_t _done; \
    asm volatile("{\n\t.reg .pred p;\n\tmbarrier.try_wait.parity.acquire.cta.shared::cta.b64 p, [%1], 0;\n\tselp.b32 %0, 1, 0, p;\n\t}" \
        : "=r"(_done) : "r"(_m) : "memory"); \
    if (!_done) { \
        asm volatile("{\n\t.reg .pred P1;\n\tWL_%=:\n\tmbarrier.try_wait.parity.acquire.cta.shared::cta.b64 P1, [%0], 0, 0x989680;\n\t@P1 bra.uni WD_%=;\n\tbra.uni WL_%=;\n\tWD_%=:\n\t}" \
            :: "r"(_m) : "memory"); \
    } \
} while (0)

__device__ __forceinline__ void split_bf(float v, __nv_bfloat16& h, __nv_bfloat16& l) {
    h = __float2bfloat16(v);
    l = __float2bfloat16(v - __bfloat162float(h));
}

// ---------------- kernel 1: merged prep (params tiles + X tiles + zero accs) ----------------
// grid 3072 x 64: blocks [0,1024) -> per-m params; [1024,3072) -> per-b X split.
__global__ void prep(const float* __restrict__ X,
                     const float* __restrict__ Mu0,
                     const float* __restrict__ Mu1,
                     const float* __restrict__ S0,
                     const float* __restrict__ S1,
                     const float* __restrict__ Lam,
                     const float* __restrict__ tp,
                     const float* __restrict__ ep) {
    int blk = blockIdx.x;
    int d = threadIdx.x;      // 64 threads

    if (blk < M_SZ) {
        int m = blk;
        float t   = tp[0];
        float eps = ep[0];
        float eps2 = eps * eps;
        float eps4 = eps2 * eps2;
        float omt  = 1.0f - t;

        int id = m * D_SZ + d;
        float s0  = S0[id], s1 = S1[id];
        float mu0 = Mu0[id], mu1 = Mu1[id];

        float Ds = sqrtf(4.0f * s0 * s1 + eps4);
        float Cs = 0.5f * (Ds - eps2);
        float mt = omt * mu0 + t * mu1;
        float Sg = omt * omt * s0 + t * t * s1 + 2.0f * t * omt * (Cs + 0.5f * eps2);
        float Pt = t * s1 + omt * Cs;
        float Qt = omt * s0 + t * Cs;
        float St = Pt - Qt - eps2 * t;
        float inv = 1.0f / Sg;
        float Kk  = St * inv;
        float v   = mu1 - mu0;
        float c   = v - Kk * mt;

        int mb = m >> 7, mr = m & 127;
        __nv_bfloat16 h, l;
        split_bf(inv, h, l);
        g_Bmh[mb * TILE_ELEMS + (tile_off(mr, d) >> 1)] = h;
        g_Bml[mb * TILE_ELEMS + (tile_off(mr, d) >> 1)] = l;
        split_bf(-2.0f * mt * inv, h, l);
        g_Bmh[mb * TILE_ELEMS + (tile_off(mr, D_SZ + d) >> 1)] = h;
        g_Bml[mb * TILE_ELEMS + (tile_off(mr, D_SZ + d) >> 1)] = l;
        split_bf(Kk, h, l);
        g_PTh[mb * TILE_ELEMS + (tile_off(d, mr) >> 1)] = h;
        g_PTl[mb * TILE_ELEMS + (tile_off(d, mr) >> 1)] = l;
        split_bf(c, h, l);
        g_PTh[mb * TILE_ELEMS + (tile_off(D_SZ + d, mr) >> 1)] = h;
        g_PTl[mb * TILE_ELEMS + (tile_off(D_SZ + d, mr) >> 1)] = l;

        __shared__ float red[64];
        red[d] = mt * mt * inv + logf(Sg);
        __syncthreads();
        #pragma unroll
        for (int s = 32; s > 0; s >>= 1) {
            if (d < s) red[d] += red[d + s];
            __syncthreads();
        }
        if (d == 0) g_hl[m] = make_float2(-0.5f * red[0], Lam[m]);
    } else {
        int b = blk - M_SZ;
        int bb = b >> 7, br = b & 127;
        float x = X[b * D_SZ + d];
        __nv_bfloat16 h, l;
        split_bf(x * x, h, l);
        g_Xh[bb * TILE_ELEMS + (tile_off(br, d) >> 1)] = h;
        g_Xl[bb * TILE_ELEMS + (tile_off(br, d) >> 1)] = l;
        split_bf(x, h, l);
        g_Xh[bb * TILE_ELEMS + (tile_off(br, D_SZ + d) >> 1)] = h;
        g_Xl[bb * TILE_ELEMS + (tile_off(br, D_SZ + d) >> 1)] = l;
        // zero accumulators / counters (same stream -> ordered before fused_mma)
        g_uacc[(size_t)b * KDIM + d] = 0.0f;
        g_uacc[(size_t)b * KDIM + D_SZ + d] = 0.0f;
        if (d == 0) g_nacc[b] = 0.0f;
        if (d == 0 && br == 0) g_cnt[bb] = 0;
    }
}

// ================= warp-MMA core =================
// 512 threads = 16 warps, warp grid 4(m) x 4(n); warp tile 32 x 32.
// C ~= (Ah+Al)(Bh+Bl)^T with hh+hl+lh (ll dropped), K = 128.
__device__ __forceinline__ void gemm_core(float acc[2][4][4],
                                          uint32_t sAh, uint32_t sAl,
                                          uint32_t sBh, uint32_t sBl,
                                          int warp_m, int warp_n, int lane) {
    int s  = lane & 7;
    int q8 = (lane >> 3) & 1;
    int hi = lane >> 4;

    #pragma unroll
    for (int k = 0; k < 8; k++) {
        uint32_t cx = (uint32_t)(((2 * k + hi) ^ s) << 4);

        uint32_t ah[2][4], al[2][4], bh[2][4], bl[2][4];
        #pragma unroll
        for (int mi = 0; mi < 2; mi++) {
            int rA = warp_m * 32 + mi * 16 + s + (q8 << 3);
            uint32_t off = (uint32_t)(rA * 256) + cx;
            ldmx4(ah[mi], sAh + off);
            ldmx4(al[mi], sAl + off);
        }
        #pragma unroll
        for (int nt = 0; nt < 2; nt++) {
            int rB = warp_n * 32 + nt * 16 + s + (q8 << 3);
            uint32_t off = (uint32_t)(rB * 256) + cx;
            ldmx4(bh[nt], sBh + off);
            ldmx4(bl[nt], sBl + off);
        }

        #pragma unroll
        for (int mi = 0; mi < 2; mi++)
            #pragma unroll
            for (int nt = 0; nt < 2; nt++)
                #pragma unroll
                for (int sb = 0; sb < 2; sb++)
                    mma16816(acc[mi][nt * 2 + sb], ah[mi], bh[nt][sb], bh[nt][sb + 2]);
        #pragma unroll
        for (int mi = 0; mi < 2; mi++)
            #pragma unroll
            for (int nt = 0; nt < 2; nt++)
                #pragma unroll
                for (int sb = 0; sb < 2; sb++)
                    mma16816(acc[mi][nt * 2 + sb], ah[mi], bl[nt][sb], bl[nt][sb + 2]);
        #pragma unroll
        for (int mi = 0; mi < 2; mi++)
            #pragma unroll
            for (int nt = 0; nt < 2; nt++)
                #pragma unroll
                for (int sb = 0; sb < 2; sb++)
                    mma16816(acc[mi][nt * 2 + sb], al[mi], bh[nt][sb], bh[nt][sb + 2]);
    }
}

// ---------------- fused kernel: GEMM1 -> exp (W in smem) -> GEMM2 -> REDG -> last-CTA finalize ----------------
// grid (8 mb, 16 bb) = 128 CTAs, 512 threads, 128KB dyn smem.
__global__ __launch_bounds__(512) void fused_mma(const float* __restrict__ X,
                                                 float* __restrict__ out) {
    extern __shared__ char smem[];
    __shared__ float2 s_hl[128];
    __shared__ float  s_nsum[128];
    __shared__ int    s_last;
    __shared__ __align__(8) unsigned long long s_mbar0, s_mbar1;

    int tx = threadIdx.x, wid = tx >> 5, lane = tx & 31;
    int warp_m = wid & 3, warp_n = wid >> 2;
    int g = lane >> 2, t = lane & 3;
    int mb = blockIdx.x;
    int bb = blockIdx.y;
    int mcol0 = mb * 128;
    int brow0 = bb * 128;

    uint32_t b0 = smem_u32(smem);            // X hi -> W hi
    uint32_t b1 = b0 + TILE_BYTES;           // X lo -> W lo
    uint32_t b2 = b0 + 2 * TILE_BYTES;       // Bm hi -> PT hi
    uint32_t b3 = b0 + 3 * TILE_BYTES;       // Bm lo -> PT lo

    if (tx == 0) { MBAR_INIT(smem_u32(&s_mbar0), 1); MBAR_INIT(smem_u32(&s_mbar1), 1); }
    if (tx < 128) { s_hl[tx] = g_hl[mcol0 + tx]; s_nsum[tx] = 0.0f; }
    __syncthreads();

    if (tx == 0) {
        uint32_t m0 = smem_u32(&s_mbar0);
        MBAR_EXPECT(m0, 4 * TILE_BYTES);
        bulk_cp(b0, g_Xh  + (size_t)bb * TILE_ELEMS, TILE_BYTES, m0);
        bulk_cp(b1, g_Xl  + (size_t)bb * TILE_ELEMS, TILE_BYTES, m0);
        bulk_cp(b2, g_Bmh + (size_t)mb * TILE_ELEMS, TILE_BYTES, m0);
        bulk_cp(b3, g_Bml + (size_t)mb * TILE_ELEMS, TILE_BYTES, m0);
    }
    MBAR_WAIT0(smem_u32(&s_mbar0));

    float acc[2][4][4];
    #pragma unroll
    for (int i = 0; i < 2; i++)
        #pragma unroll
        for (int j = 0; j < 4; j++)
            #pragma unroll
            for (int e = 0; e < 4; e++) acc[i][j][e] = 0.0f;

    // GEMM1: S = Xcat @ Bm^T
    gemm_core(acc, b0, b1, b2, b3, warp_m, warp_n, lane);

    __syncthreads();   // everyone done reading X and Bm

    // kick off PT load into buf2/3 (overlaps the exp epilogue below)
    if (tx == 0) {
        uint32_t m1 = smem_u32(&s_mbar1);
        MBAR_EXPECT(m1, 2 * TILE_BYTES);
        bulk_cp(b2, g_PTh + (size_t)mb * TILE_ELEMS, TILE_BYTES, m1);
        bulk_cp(b3, g_PTl + (size_t)mb * TILE_ELEMS, TILE_BYTES, m1);
    }

    // epilogue: exp -> W (hi/lo) into buf0/buf1 (swizzled), norm partials
    #pragma unroll
    for (int mi = 0; mi < 2; mi++) {
        int r0 = warp_m * 32 + mi * 16 + g;     // local b row
        int r1 = r0 + 8;
        float ns0 = 0.0f, ns1 = 0.0f;
        #pragma unroll
        for (int n8 = 0; n8 < 4; n8++) {
            int ml = warp_n * 32 + n8 * 8 + t * 2;    // local m col
            float2 hlA = s_hl[ml], hlB = s_hl[ml + 1];
            float* c = acc[mi][n8];

            float lw0 = fmaf(c[0], -0.5f, hlA.x); lw0 = fminf(fmaxf(lw0, -50.f), 50.f);
            float lw1 = fmaf(c[1], -0.5f, hlB.x); lw1 = fminf(fmaxf(lw1, -50.f), 50.f);
            float lw2 = fmaf(c[2], -0.5f, hlA.x); lw2 = fminf(fmaxf(lw2, -50.f), 50.f);
            float lw3 = fmaf(c[3], -0.5f, hlB.x); lw3 = fminf(fmaxf(lw3, -50.f), 50.f);
            float w0 = __expf(lw0) * hlA.y;
            float w1 = __expf(lw1) * hlB.y;
            float w2 = __expf(lw2) * hlA.y;
            float w3 = __expf(lw3) * hlB.y;
            ns0 += w0 + w1;
            ns1 += w2 + w3;

            __nv_bfloat16 h, l;
            __nv_bfloat162 ph, pl;
            split_bf(w0, h, l); ph.x = h; pl.x = l;
            split_bf(w1, h, l); ph.y = h; pl.y = l;
            uint32_t o0 = tile_off(r0, ml);
            *(__nv_bfloat162*)(smem + o0) = ph;
            *(__nv_bfloat162*)(smem + TILE_BYTES + o0) = pl;
            split_bf(w2, h, l); ph.x = h; pl.x = l;
            split_bf(w3, h, l); ph.y = h; pl.y = l;
            uint32_t o1 = tile_off(r1, ml);
            *(__nv_bfloat162*)(smem + o1) = ph;
            *(__nv_bfloat162*)(smem + TILE_BYTES + o1) = pl;
        }
        ns0 += __shfl_xor_sync(0xFFFFFFFF, ns0, 1);
        ns0 += __shfl_xor_sync(0xFFFFFFFF, ns0, 2);
        ns1 += __shfl_xor_sync(0xFFFFFFFF, ns1, 1);
        ns1 += __shfl_xor_sync(0xFFFFFFFF, ns1, 2);
        if (t == 0) {
            atomicAdd(&s_nsum[r0], ns0);
            atomicAdd(&s_nsum[r1], ns1);
        }
    }
    __syncthreads();   // W writes visible to all warps
    if (tx < 128) atomicAdd(&g_nacc[brow0 + tx], s_nsum[tx]);

    MBAR_WAIT0(smem_u32(&s_mbar1));   // PT tiles ready

    // GEMM2: u-partial = W @ PT^T, reduced over mb via REDG
    #pragma unroll
    for (int i = 0; i < 2; i++)
        #pragma unroll
        for (int j = 0; j < 4; j++)
            #pragma unroll
            for (int e = 0; e < 4; e++) acc[i][j][e] = 0.0f;

    gemm_core(acc, b0, b1, b2, b3, warp_m, warp_n, lane);

    #pragma unroll
    for (int mi = 0; mi < 2; mi++) {
        int r0 = brow0 + warp_m * 32 + mi * 16 + g;
        int r1 = r0 + 8;
        #pragma unroll
        for (int n8 = 0; n8 < 4; n8++) {
            int col = warp_n * 32 + n8 * 8 + t * 2;
            float* c = acc[mi][n8];
            atomicAdd(&g_uacc[(size_t)r0 * KDIM + col],     c[0]);
            atomicAdd(&g_uacc[(size_t)r0 * KDIM + col + 1], c[1]);
            atomicAdd(&g_uacc[(size_t)r1 * KDIM + col],     c[2]);
            atomicAdd(&g_uacc[(size_t)r1 * KDIM + col + 1], c[3]);
        }
    }

    // ---- last-CTA finalize for this b block ----
    __threadfence();
    __syncthreads();
    if (tx == 0) s_last = atomicAdd(&g_cnt[bb], 1);
    __syncthreads();
    if (s_last == 7) {
        // all 8 mb chunks done for rows [brow0, brow0+128)
        #pragma unroll
        for (int i = 0; i < 16; i++) {
            int idx = tx + i * 512;            // 0..8191 = 128 rows x 64 cols
            int b = brow0 + (idx >> 6);
            int d = idx & 63;
            float t1 = g_uacc[(size_t)b * KDIM + d];
            float t2 = g_uacc[(size_t)b * KDIM + D_SZ + d];
            float nr = g_nacc[b];
            out[b * D_SZ + d] = (X[b * D_SZ + d] * t1 + t2) / nr;
        }
    }
}

// ---------------- launch ----------------
#define DYN_SMEM (4 * TILE_BYTES)   // 128KB

extern "C" void kernel_launch(void* const* d_in, const int* in_sizes, int n_in,
                              void* d_out, int out_size) {
    const float* X   = (const float*)d_in[0];
    const float* Mu0 = (const float*)d_in[1];
    const float* Mu1 = (const float*)d_in[2];
    const float* S0  = (const float*)d_in[3];
    const float* S1  = (const float*)d_in[4];
    const float* Lam = (const float*)d_in[5];
    const float* tp  = (const float*)d_in[6];
    const float* ep  = (const float*)d_in[7];
    float* out = (float*)d_out;

    cudaFuncSetAttribute(fused_mma, cudaFuncAttributeMaxDynamicSharedMemorySize, DYN_SMEM);

    prep<<<M_SZ + B_SZ, 64>>>(X, Mu0, Mu1, S0, S1, Lam, tp, ep);
    fused_mma<<<dim3(8, 16), 512, DYN_SMEM>>>(X, out);
}

// round 15
// speedup vs baseline: 1.2323x; 1.2323x over previous
#include <cuda_runtime.h>
#include <cuda_bf16.h>
#include <math.h>
#include <stdint.h>

#define B_SZ 2048
#define M_SZ 1024
#define D_SZ 64
#define KDIM 128   // 2*D_SZ
#define TILE_ELEMS 16384   // 128x128 bf16 tile
#define TILE_BYTES 32768

// ---------------- device scratch (operands stored as swizzled 128x128 tiles) ----------------
__device__ __nv_bfloat16 g_Xh[16 * TILE_ELEMS];          // [bblock][tile]
__device__ __nv_bfloat16 g_Xl[16 * TILE_ELEMS];
__device__ __nv_bfloat16 g_Bmh[8 * TILE_ELEMS];          // [mblock][tile] rows=m, cols=k
__device__ __nv_bfloat16 g_Bml[8 * TILE_ELEMS];
__device__ __nv_bfloat16 g_PTh[8 * TILE_ELEMS];          // [mblock][tile] rows=outcol, cols=m
__device__ __nv_bfloat16 g_PTl[8 * TILE_ELEMS];
__device__ float2 g_hl[M_SZ];                    // (.x = -0.5*sum(mut^2/Sig + log Sig), .y = Lam)
__device__ float  g_uacc[(size_t)B_SZ * KDIM];   // [b][T1|T2] atomically reduced over mb
__device__ float  g_nacc[B_SZ];                  // norm, atomically reduced

// ---------------- helpers ----------------
__device__ __forceinline__ uint32_t smem_u32(const void* p) {
    uint32_t a;
    asm("{ .reg .u64 t; cvta.to.shared.u64 t, %1; cvt.u32.u64 %0, t; }" : "=r"(a) : "l"(p));
    return a;
}
// byte offset of element (r, c) inside a swizzled 128x128 bf16 tile
__device__ __forceinline__ uint32_t tile_off(int r, int c) {
    int ch = c >> 3;
    return (uint32_t)(r * 256 + (((ch ^ (r & 7))) << 4) + ((c & 7) << 1));
}
__device__ __forceinline__ void ldmx4(uint32_t* r, uint32_t addr) {
    asm volatile("ldmatrix.sync.aligned.m8n8.x4.shared.b16 {%0,%1,%2,%3}, [%4];"
        : "=r"(r[0]), "=r"(r[1]), "=r"(r[2]), "=r"(r[3]) : "r"(addr));
}
__device__ __forceinline__ void mma16816(float* c, const uint32_t* a, uint32_t b0, uint32_t b1) {
    asm volatile(
        "mma.sync.aligned.m16n8k16.row.col.f32.bf16.bf16.f32 "
        "{%0,%1,%2,%3}, {%4,%5,%6,%7}, {%8,%9}, {%0,%1,%2,%3};"
        : "+f"(c[0]), "+f"(c[1]), "+f"(c[2]), "+f"(c[3])
        : "r"(a[0]), "r"(a[1]), "r"(a[2]), "r"(a[3]), "r"(b0), "r"(b1));
}
__device__ __forceinline__ void bulk_cp(uint32_t dst, const void* src, uint32_t bytes, uint32_t mbar) {
    asm volatile(
        "cp.async.bulk.shared::cluster.global.mbarrier::complete_tx::bytes [%0], [%1], %2, [%3];"
        :: "r"(dst), "l"(src), "r"(bytes), "r"(mbar) : "memory");
}
#define MBAR_INIT(a, n) asm volatile("mbarrier.init.shared.b64 [%0], %1;" :: "r"(a), "r"(n) : "memory")
#define MBAR_EXPECT(a, b) asm volatile("mbarrier.arrive.expect_tx.shared.b64 _, [%0], %1;" :: "r"(a), "r"(b) : "memory")
#define MBAR_WAIT0(a) do { \
    uint32_t _m = (a); uint32_t _done; \
    asm volatile("{\n\t.reg .pred p;\n\tmbarrier.try_wait.parity.acquire.cta.shared::cta.b64 p, [%1], 0;\n\tselp.b32 %0, 1, 0, p;\n\t}" \
        : "=r"(_done) : "r"(_m) : "memory"); \
    if (!_done) { \
        asm volatile("{\n\t.reg .pred P1;\n\tWL_%=:\n\tmbarrier.try_wait.parity.acquire.cta.shared::cta.b64 P1, [%0], 0, 0x989680;\n\t@P1 bra.uni WD_%=;\n\tbra.uni WL_%=;\n\tWD_%=:\n\t}" \
            :: "r"(_m) : "memory"); \
    } \
} while (0)

__device__ __forceinline__ void split_bf(float v, __nv_bfloat16& h, __nv_bfloat16& l) {
    h = __float2bfloat16(v);
    l = __float2bfloat16(v - __bfloat162float(h));
}

// ---------------- kernel 1: merged prep (params tiles + X tiles + zero accs) ----------------
// grid 3072 x 64: blocks [0,1024) -> per-m params; [1024,3072) -> per-b X split.
__global__ void prep(const float* __restrict__ X,
                     const float* __restrict__ Mu0,
                     const float* __restrict__ Mu1,
                     const float* __restrict__ S0,
                     const float* __restrict__ S1,
                     const float* __restrict__ Lam,
                     const float* __restrict__ tp,
                     const float* __restrict__ ep) {
    int blk = blockIdx.x;
    int d = threadIdx.x;      // 64 threads

    if (blk < M_SZ) {
        int m = blk;
        float t   = tp[0];
        float eps = ep[0];
        float eps2 = eps * eps;
        float eps4 = eps2 * eps2;
        float omt  = 1.0f - t;

        int id = m * D_SZ + d;
        float s0  = S0[id], s1 = S1[id];
        float mu0 = Mu0[id], mu1 = Mu1[id];

        float Ds = sqrtf(4.0f * s0 * s1 + eps4);
        float Cs = 0.5f * (Ds - eps2);
        float mt = omt * mu0 + t * mu1;
        float Sg = omt * omt * s0 + t * t * s1 + 2.0f * t * omt * (Cs + 0.5f * eps2);
        float Pt = t * s1 + omt * Cs;
        float Qt = omt * s0 + t * Cs;
        float St = Pt - Qt - eps2 * t;
        float inv = 1.0f / Sg;
        float Kk  = St * inv;
        float v   = mu1 - mu0;
        float c   = v - Kk * mt;

        int mb = m >> 7, mr = m & 127;
        __nv_bfloat16 h, l;
        split_bf(inv, h, l);
        g_Bmh[mb * TILE_ELEMS + (tile_off(mr, d) >> 1)] = h;
        g_Bml[mb * TILE_ELEMS + (tile_off(mr, d) >> 1)] = l;
        split_bf(-2.0f * mt * inv, h, l);
        g_Bmh[mb * TILE_ELEMS + (tile_off(mr, D_SZ + d) >> 1)] = h;
        g_Bml[mb * TILE_ELEMS + (tile_off(mr, D_SZ + d) >> 1)] = l;
        split_bf(Kk, h, l);
        g_PTh[mb * TILE_ELEMS + (tile_off(d, mr) >> 1)] = h;
        g_PTl[mb * TILE_ELEMS + (tile_off(d, mr) >> 1)] = l;
        split_bf(c, h, l);
        g_PTh[mb * TILE_ELEMS + (tile_off(D_SZ + d, mr) >> 1)] = h;
        g_PTl[mb * TILE_ELEMS + (tile_off(D_SZ + d, mr) >> 1)] = l;

        __shared__ float red[64];
        red[d] = mt * mt * inv + logf(Sg);
        __syncthreads();
        #pragma unroll
        for (int s = 32; s > 0; s >>= 1) {
            if (d < s) red[d] += red[d + s];
            __syncthreads();
        }
        if (d == 0) g_hl[m] = make_float2(-0.5f * red[0], Lam[m]);
    } else {
        int b = blk - M_SZ;
        int bb = b >> 7, br = b & 127;
        float x = X[b * D_SZ + d];
        __nv_bfloat16 h, l;
        split_bf(x * x, h, l);
        g_Xh[bb * TILE_ELEMS + (tile_off(br, d) >> 1)] = h;
        g_Xl[bb * TILE_ELEMS + (tile_off(br, d) >> 1)] = l;
        split_bf(x, h, l);
        g_Xh[bb * TILE_ELEMS + (tile_off(br, D_SZ + d) >> 1)] = h;
        g_Xl[bb * TILE_ELEMS + (tile_off(br, D_SZ + d) >> 1)] = l;
        // zero accumulators (same stream -> ordered before fused_mma)
        g_uacc[(size_t)b * KDIM + d] = 0.0f;
        g_uacc[(size_t)b * KDIM + D_SZ + d] = 0.0f;
        if (d == 0) g_nacc[b] = 0.0f;
    }
}

// ================= warp-MMA core =================
// 512 threads = 16 warps, warp grid 4(m) x 4(n); warp tile 32 x 32.
// C ~= (Ah+Al)(Bh+Bl)^T with hh+hl+lh (ll dropped), K = 128.
__device__ __forceinline__ void gemm_core(float acc[2][4][4],
                                          uint32_t sAh, uint32_t sAl,
                                          uint32_t sBh, uint32_t sBl,
                                          int warp_m, int warp_n, int lane) {
    int s  = lane & 7;
    int q8 = (lane >> 3) & 1;
    int hi = lane >> 4;

    #pragma unroll
    for (int k = 0; k < 8; k++) {
        uint32_t cx = (uint32_t)(((2 * k + hi) ^ s) << 4);

        uint32_t ah[2][4], al[2][4], bh[2][4], bl[2][4];
        #pragma unroll
        for (int mi = 0; mi < 2; mi++) {
            int rA = warp_m * 32 + mi * 16 + s + (q8 << 3);
            uint32_t off = (uint32_t)(rA * 256) + cx;
            ldmx4(ah[mi], sAh + off);
            ldmx4(al[mi], sAl + off);
        }
        #pragma unroll
        for (int nt = 0; nt < 2; nt++) {
            int rB = warp_n * 32 + nt * 16 + s + (q8 << 3);
            uint32_t off = (uint32_t)(rB * 256) + cx;
            ldmx4(bh[nt], sBh + off);
            ldmx4(bl[nt], sBl + off);
        }

        #pragma unroll
        for (int mi = 0; mi < 2; mi++)
            #pragma unroll
            for (int nt = 0; nt < 2; nt++)
                #pragma unroll
                for (int sb = 0; sb < 2; sb++)
                    mma16816(acc[mi][nt * 2 + sb], ah[mi], bh[nt][sb], bh[nt][sb + 2]);
        #pragma unroll
        for (int mi = 0; mi < 2; mi++)
            #pragma unroll
            for (int nt = 0; nt < 2; nt++)
                #pragma unroll
                for (int sb = 0; sb < 2; sb++)
                    mma16816(acc[mi][nt * 2 + sb], ah[mi], bl[nt][sb], bl[nt][sb + 2]);
        #pragma unroll
        for (int mi = 0; mi < 2; mi++)
            #pragma unroll
            for (int nt = 0; nt < 2; nt++)
                #pragma unroll
                for (int sb = 0; sb < 2; sb++)
                    mma16816(acc[mi][nt * 2 + sb], al[mi], bh[nt][sb], bh[nt][sb + 2]);
    }
}

// ---------------- fused kernel: GEMM1 -> exp (W in smem) -> GEMM2 -> REDG (no fence) ----------------
// grid (8 mb, 16 bb) = 128 CTAs, 512 threads, 128KB dyn smem.
__global__ __launch_bounds__(512) void fused_mma() {
    extern __shared__ char smem[];
    __shared__ float2 s_hl[128];
    __shared__ float  s_nsum[128];
    __shared__ __align__(8) unsigned long long s_mbar0, s_mbar1;

    int tx = threadIdx.x, wid = tx >> 5, lane = tx & 31;
    int warp_m = wid & 3, warp_n = wid >> 2;
    int g = lane >> 2, t = lane & 3;
    int mb = blockIdx.x;
    int bb = blockIdx.y;
    int mcol0 = mb * 128;
    int brow0 = bb * 128;

    uint32_t b0 = smem_u32(smem);            // X hi -> W hi
    uint32_t b1 = b0 + TILE_BYTES;           // X lo -> W lo
    uint32_t b2 = b0 + 2 * TILE_BYTES;       // Bm hi -> PT hi
    uint32_t b3 = b0 + 3 * TILE_BYTES;       // Bm lo -> PT lo

    if (tx == 0) { MBAR_INIT(smem_u32(&s_mbar0), 1); MBAR_INIT(smem_u32(&s_mbar1), 1); }
    if (tx < 128) { s_hl[tx] = g_hl[mcol0 + tx]; s_nsum[tx] = 0.0f; }
    __syncthreads();

    if (tx == 0) {
        uint32_t m0 = smem_u32(&s_mbar0);
        MBAR_EXPECT(m0, 4 * TILE_BYTES);
        bulk_cp(b0, g_Xh  + (size_t)bb * TILE_ELEMS, TILE_BYTES, m0);
        bulk_cp(b1, g_Xl  + (size_t)bb * TILE_ELEMS, TILE_BYTES, m0);
        bulk_cp(b2, g_Bmh + (size_t)mb * TILE_ELEMS, TILE_BYTES, m0);
        bulk_cp(b3, g_Bml + (size_t)mb * TILE_ELEMS, TILE_BYTES, m0);
    }
    MBAR_WAIT0(smem_u32(&s_mbar0));

    float acc[2][4][4];
    #pragma unroll
    for (int i = 0; i < 2; i++)
        #pragma unroll
        for (int j = 0; j < 4; j++)
            #pragma unroll
            for (int e = 0; e < 4; e++) acc[i][j][e] = 0.0f;

    // GEMM1: S = Xcat @ Bm^T
    gemm_core(acc, b0, b1, b2, b3, warp_m, warp_n, lane);

    __syncthreads();   // everyone done reading X and Bm

    // kick off PT load into buf2/3 (overlaps the exp epilogue below)
    if (tx == 0) {
        uint32_t m1 = smem_u32(&s_mbar1);
        MBAR_EXPECT(m1, 2 * TILE_BYTES);
        bulk_cp(b2, g_PTh + (size_t)mb * TILE_ELEMS, TILE_BYTES, m1);
        bulk_cp(b3, g_PTl + (size_t)mb * TILE_ELEMS, TILE_BYTES, m1);
    }

    // epilogue: exp -> W (hi/lo) into buf0/buf1 (swizzled), norm partials
    #pragma unroll
    for (int mi = 0; mi < 2; mi++) {
        int r0 = warp_m * 32 + mi * 16 + g;     // local b row
        int r1 = r0 + 8;
        float ns0 = 0.0f, ns1 = 0.0f;
        #pragma unroll
        for (int n8 = 0; n8 < 4; n8++) {
            int ml = warp_n * 32 + n8 * 8 + t * 2;    // local m col
            float2 hlA = s_hl[ml], hlB = s_hl[ml + 1];
            float* c = acc[mi][n8];

            float lw0 = fmaf(c[0], -0.5f, hlA.x); lw0 = fminf(fmaxf(lw0, -50.f), 50.f);
            float lw1 = fmaf(c[1], -0.5f, hlB.x); lw1 = fminf(fmaxf(lw1, -50.f), 50.f);
            float lw2 = fmaf(c[2], -0.5f, hlA.x); lw2 = fminf(fmaxf(lw2, -50.f), 50.f);
            float lw3 = fmaf(c[3], -0.5f, hlB.x); lw3 = fminf(fmaxf(lw3, -50.f), 50.f);
            float w0 = __expf(lw0) * hlA.y;
            float w1 = __expf(lw1) * hlB.y;
            float w2 = __expf(lw2) * hlA.y;
            float w3 = __expf(lw3) * hlB.y;
            ns0 += w0 + w1;
            ns1 += w2 + w3;

            __nv_bfloat16 h, l;
            __nv_bfloat162 ph, pl;
            split_bf(w0, h, l); ph.x = h; pl.x = l;
            split_bf(w1, h, l); ph.y = h; pl.y = l;
            uint32_t o0 = tile_off(r0, ml);
            *(__nv_bfloat162*)(smem + o0) = ph;
            *(__nv_bfloat162*)(smem + TILE_BYTES + o0) = pl;
            split_bf(w2, h, l); ph.x = h; pl.x = l;
            split_bf(w3, h, l); ph.y = h; pl.y = l;
            uint32_t o1 = tile_off(r1, ml);
            *(__nv_bfloat162*)(smem + o1) = ph;
            *(__nv_bfloat162*)(smem + TILE_BYTES + o1) = pl;
        }
        ns0 += __shfl_xor_sync(0xFFFFFFFF, ns0, 1);
        ns0 += __shfl_xor_sync(0xFFFFFFFF, ns0, 2);
        ns1 += __shfl_xor_sync(0xFFFFFFFF, ns1, 1);
        ns1 += __shfl_xor_sync(0xFFFFFFFF, ns1, 2);
        if (t == 0) {
            atomicAdd(&s_nsum[r0], ns0);
            atomicAdd(&s_nsum[r1], ns1);
        }
    }
    __syncthreads();   // W writes visible to all warps
    if (tx < 128) atomicAdd(&g_nacc[brow0 + tx], s_nsum[tx]);

    MBAR_WAIT0(smem_u32(&s_mbar1));   // PT tiles ready

    // GEMM2: u-partial = W @ PT^T, reduced over mb via REDG (fire-and-forget)
    #pragma unroll
    for (int i = 0; i < 2; i++)
        #pragma unroll
        for (int j = 0; j < 4; j++)
            #pragma unroll
            for (int e = 0; e < 4; e++) acc[i][j][e] = 0.0f;

    gemm_core(acc, b0, b1, b2, b3, warp_m, warp_n, lane);

    #pragma unroll
    for (int mi = 0; mi < 2; mi++) {
        int r0 = brow0 + warp_m * 32 + mi * 16 + g;
        int r1 = r0 + 8;
        #pragma unroll
        for (int n8 = 0; n8 < 4; n8++) {
            int col = warp_n * 32 + n8 * 8 + t * 2;
            float* c = acc[mi][n8];
            atomicAdd(&g_uacc[(size_t)r0 * KDIM + col],     c[0]);
            atomicAdd(&g_uacc[(size_t)r0 * KDIM + col + 1], c[1]);
            atomicAdd(&g_uacc[(size_t)r1 * KDIM + col],     c[2]);
            atomicAdd(&g_uacc[(size_t)r1 * KDIM + col + 1], c[3]);
        }
    }
}

// ---------------- kernel 3: finalize ----------------
__global__ void finalize(const float* __restrict__ X, float* __restrict__ out) {
    int i = blockIdx.x * blockDim.x + threadIdx.x;   // 0..B*64-1
    int b = i >> 6, d = i & 63;
    float t1 = g_uacc[(size_t)b * KDIM + d];
    float t2 = g_uacc[(size_t)b * KDIM + D_SZ + d];
    float nr = g_nacc[b];
    out[i] = (X[i] * t1 + t2) / nr;
}

// ---------------- launch ----------------
#define DYN_SMEM (4 * TILE_BYTES)   // 128KB

extern "C" void kernel_launch(void* const* d_in, const int* in_sizes, int n_in,
                              void* d_out, int out_size) {
    const float* X   = (const float*)d_in[0];
    const float* Mu0 = (const float*)d_in[1];
    const float* Mu1 = (const float*)d_in[2];
    const float* S0  = (const float*)d_in[3];
    const float* S1  = (const float*)d_in[4];
    const float* Lam = (const float*)d_in[5];
    const float* tp  = (const float*)d_in[6];
    const float* ep  = (const float*)d_in[7];
    float* out = (float*)d_out;

    cudaFuncSetAttribute(fused_mma, cudaFuncAttributeMaxDynamicSharedMemorySize, DYN_SMEM);

    prep<<<M_SZ + B_SZ, 64>>>(X, Mu0, Mu1, S0, S1, Lam, tp, ep);
    fused_mma<<<dim3(8, 16), 512, DYN_SMEM>>>();
    finalize<<<(B_SZ * D_SZ) / 256, 256>>>(X, out);
}